// round 8
// baseline (speedup 1.0000x reference)
#include <cuda_runtime.h>
#include <cuda_bf16.h>
#include <math.h>

// Problem shape (fixed by reference setup_inputs)
#define B 256
#define S 512
#define D 768
#define C 2
#define SPLIT 8                 // S-splits per sample for parallelism
#define SPB (S / SPLIT)         // 64 s-rows per block
#define VEC_T 192               // D/4 float4 lanes per block (768/4)

// Scratch (device globals — no allocation allowed).
__device__ float g_part[SPLIT * B * D];  // partial masked sums [sp][b][d]
__device__ float g_nll[B];
__device__ int   g_mask_kind;            // 0=uint8, 1=int32, 2=float32

// ---------------------------------------------------------------------------
// Kernel 0: sniff the mask dtype. 128 threads, one word each (parallel,
// deterministic). int32 0/1 masks -> every word in {0,1}; float32 0/1 masks
// -> every word in {0, 0x3F800000}; random bool bytes fail both.
// ---------------------------------------------------------------------------
__global__ __launch_bounds__(128) void detect_mask_kind_kernel(
    const unsigned int* __restrict__ mw)
{
    __shared__ int ok_int, ok_f;
    const int t = threadIdx.x;
    if (t == 0) { ok_int = 1; ok_f = 1; }
    __syncthreads();

    const unsigned int v = mw[t];
    if (v != 0u && v != 1u)          atomicAnd(&ok_int, 0);
    if (v != 0u && v != 0x3F800000u) atomicAnd(&ok_f, 0);
    __syncthreads();

    if (t == 0) g_mask_kind = ok_int ? 1 : (ok_f ? 2 : 0);
}

__device__ __forceinline__ int mask_at(const void* __restrict__ mask,
                                       int kind, size_t idx)
{
    if (kind == 1) return ((const int*)mask)[idx] != 0;
    if (kind == 2) return ((const float*)mask)[idx] != 0.0f;
    return ((const unsigned char*)mask)[idx] != 0;
}

// ---------------------------------------------------------------------------
// Kernel 1: masked partial sums. grid=(B, SPLIT), block=192 threads.
// Phase A compacts this split's 64 mask bits into an ordered ABSOLUTE row
// list. Phase B is a branch-free 8-way batched accumulation so each thread
// keeps 8 independent LDG.128 in flight. Rows with mask==0 never loaded.
// ---------------------------------------------------------------------------
__global__ __launch_bounds__(VEC_T) void pool_partial_kernel(
    const float* __restrict__ x, const void* __restrict__ mask)
{
    const int b  = blockIdx.x;
    const int sp = blockIdx.y;
    const int t  = threadIdx.x;              // 0..191
    const int s0 = sp * SPB;
    const int kind = g_mask_kind;

    __shared__ int slist[SPB];
    __shared__ int wcnt[2];

    // --- Phase A: ordered compaction (warps 0 and 1; all lanes active) ---
    int m = 0, pos = 0;
    if (t < 64) {
        const int lane = t & 31;
        const int warp = t >> 5;
        m = mask_at(mask, kind, (size_t)b * S + s0 + t);
        const unsigned bal = __ballot_sync(0xFFFFFFFFu, m);
        pos = __popc(bal & ((1u << lane) - 1u));
        if (lane == 0) wcnt[warp] = __popc(bal);
    }
    __syncthreads();
    if (t < 64 && m) {
        const int base = (t >= 32) ? wcnt[0] : 0;
        slist[base + pos] = s0 + t;          // absolute row index
    }
    __syncthreads();

    const int n = wcnt[0] + wcnt[1];

    // --- Phase B: branch-free batched accumulation (8-way, then 4, then 1) ---
    const float4* __restrict__ xb =
        reinterpret_cast<const float4*>(x + (size_t)b * S * D) + t;

    float4 acc = make_float4(0.f, 0.f, 0.f, 0.f);
    int i = 0;
    for (; i + 8 <= n; i += 8) {
        float4 v[8];
#pragma unroll
        for (int j = 0; j < 8; ++j)
            v[j] = xb[(size_t)slist[i + j] * VEC_T];
#pragma unroll
        for (int j = 0; j < 8; ++j) {
            acc.x += v[j].x; acc.y += v[j].y;
            acc.z += v[j].z; acc.w += v[j].w;
        }
    }
    for (; i + 4 <= n; i += 4) {
        float4 v[4];
#pragma unroll
        for (int j = 0; j < 4; ++j)
            v[j] = xb[(size_t)slist[i + j] * VEC_T];
#pragma unroll
        for (int j = 0; j < 4; ++j) {
            acc.x += v[j].x; acc.y += v[j].y;
            acc.z += v[j].z; acc.w += v[j].w;
        }
    }
    for (; i < n; ++i) {
        const float4 v = xb[(size_t)slist[i] * VEC_T];
        acc.x += v.x; acc.y += v.y; acc.z += v.z; acc.w += v.w;
    }

    float4* __restrict__ p = reinterpret_cast<float4*>(
        g_part + ((size_t)sp * B + b) * D);
    p[t] = acc;
}

// ---------------------------------------------------------------------------
// Kernel 2: per-sample finalize. grid=B, block=256.
// ---------------------------------------------------------------------------
__global__ __launch_bounds__(256) void finalize_kernel(
    const void* __restrict__ mask,
    const float* __restrict__ w,        // [C, D]
    const float* __restrict__ bias,     // [C]
    const int* __restrict__ labels,     // [B]
    float* __restrict__ logits_out)     // may be nullptr
{
    const int b = blockIdx.x;
    const int t = threadIdx.x;
    const int kind = g_mask_kind;

    __shared__ float red[256];
    __shared__ float r0[256];
    __shared__ float r1[256];
    __shared__ float s_inv;

    // --- count masked tokens ---
    float cnt = (float)mask_at(mask, kind, (size_t)b * S + t)
              + (float)mask_at(mask, kind, (size_t)b * S + t + 256);
    red[t] = cnt;
    __syncthreads();
    for (int off = 128; off > 0; off >>= 1) {
        if (t < off) red[t] += red[t + off];
        __syncthreads();
    }
    if (t == 0) s_inv = 1.f / red[0];
    __syncthreads();
    const float inv = s_inv;

    // --- pooled + partial dot products (each thread owns 3 d-values) ---
    float p0 = 0.f, p1 = 0.f;
#pragma unroll
    for (int k = 0; k < 3; ++k) {
        const int d = t + k * 256;
        float s = 0.f;
#pragma unroll
        for (int sp = 0; sp < SPLIT; ++sp)
            s += g_part[((size_t)sp * B + b) * D + d];
        const float pooled = s * inv;
        p0 += pooled * w[d];
        p1 += pooled * w[D + d];
    }
    r0[t] = p0;
    r1[t] = p1;
    __syncthreads();
    for (int off = 128; off > 0; off >>= 1) {
        if (t < off) { r0[t] += r0[t + off]; r1[t] += r1[t + off]; }
        __syncthreads();
    }

    if (t == 0) {
        const float l0 = r0[0] + bias[0];
        const float l1 = r1[0] + bias[1];
        if (logits_out) {
            logits_out[(size_t)b * C + 0] = l0;
            logits_out[(size_t)b * C + 1] = l1;
        }
        const float m   = fmaxf(l0, l1);
        const float lse = m + logf(expf(l0 - m) + expf(l1 - m));
        const int lab   = labels[b];
        g_nll[b] = lse - (lab ? l1 : l0);
    }
}

// ---------------------------------------------------------------------------
// Kernel 3: mean NLL -> loss. 1 block of 256 threads.
// ---------------------------------------------------------------------------
__global__ __launch_bounds__(256) void loss_kernel(float* __restrict__ loss_out)
{
    const int t = threadIdx.x;
    __shared__ float red[256];
    red[t] = g_nll[t];
    __syncthreads();
    for (int off = 128; off > 0; off >>= 1) {
        if (t < off) red[t] += red[t + off];
        __syncthreads();
    }
    if (t == 0 && loss_out) *loss_out = red[0] * (1.f / (float)B);
}

// ---------------------------------------------------------------------------
extern "C" void kernel_launch(void* const* d_in, const int* in_sizes, int n_in,
                              void* d_out, int out_size)
{
    // Identify inputs by element count (all five mutually distinct).
    const float* x      = nullptr;
    const void*  mask   = nullptr;
    const int*   labels = nullptr;
    const float* w      = nullptr;
    const float* bias   = nullptr;

    for (int i = 0; i < n_in; ++i) {
        switch (in_sizes[i]) {
            case B * S * D: x      = (const float*)d_in[i]; break;
            case B * S:     mask   = d_in[i];               break;
            case B:         labels = (const int*)d_in[i];   break;
            case C * D:     w      = (const float*)d_in[i]; break;
            case C:         bias   = (const float*)d_in[i]; break;
            default: break;
        }
    }
    if (!x)      x      = (const float*)d_in[0];
    if (!mask)   mask   = d_in[1];
    if (!labels) labels = (const int*)d_in[2];
    if (!w)      w      = (const float*)d_in[3];
    if (!bias)   bias   = (const float*)d_in[4];

    float* out = (float*)d_out;

    // Output layout: flattened (loss, logits) = 1 + B*C = 513 floats.
    float* loss_ptr   = nullptr;
    float* logits_ptr = nullptr;
    if (out_size >= 1 + B * C) { loss_ptr = out; logits_ptr = out + 1; }
    else if (out_size == B * C) { logits_ptr = out; }
    else { loss_ptr = out; }

    detect_mask_kind_kernel<<<1, 128>>>((const unsigned int*)mask);
    dim3 g1(B, SPLIT);
    pool_partial_kernel<<<g1, VEC_T>>>(x, mask);
    finalize_kernel<<<B, 256>>>(mask, w, bias, labels, logits_ptr);
    loss_kernel<<<1, 256>>>(loss_ptr);
}

// round 16
// speedup vs baseline: 1.0042x; 1.0042x over previous
#include <cuda_runtime.h>
#include <cuda_bf16.h>
#include <math.h>

// Problem shape (fixed by reference setup_inputs)
#define B 256
#define S 512
#define D 768
#define C 2
#define SPLIT 8                 // S-splits per sample for parallelism
#define SPB (S / SPLIT)         // 64 s-rows per block
#define VEC_T 192               // D/4 float4 lanes per block (768/4)

// Scratch (device globals — no allocation allowed). All counters end at 0
// every launch -> graph replays see identical initial state.
__device__ float g_part[SPLIT * B * D];  // partial masked sums [sp][b][d]
__device__ float g_nll[B];
__device__ int   g_sticket[B];           // per-sample pool-completion counters
__device__ int   g_done;                 // finalize-completion counter

// ---------------------------------------------------------------------------
// Inline mask-dtype detection: first 32 words all in {0,1} -> int32 (kind 1);
// all in {0,0x3F800000} -> float32 (kind 2); else byte mask (kind 0).
// Random bool bytes pass the int32 test with P ~ 8^-32 — negligible.
// ---------------------------------------------------------------------------
__device__ __forceinline__ int detect_mask_kind(const void* __restrict__ mask)
{
    const unsigned int* mw = (const unsigned int*)mask;
    bool ai = true, af = true;
#pragma unroll
    for (int i = 0; i < 32; ++i) {
        const unsigned int v = mw[i];
        ai = ai && (v == 0u || v == 1u);
        af = af && (v == 0u || v == 0x3F800000u);
    }
    return ai ? 1 : (af ? 2 : 0);
}

__device__ __forceinline__ int mask_at(const void* __restrict__ mask,
                                       int kind, size_t idx)
{
    if (kind == 1) return ((const int*)mask)[idx] != 0;
    if (kind == 2) return ((const float*)mask)[idx] != 0.0f;
    return ((const unsigned char*)mask)[idx] != 0;
}

// ---------------------------------------------------------------------------
// Fused kernel: masked partial sums + per-sample finalize + mean loss.
// grid=(B, SPLIT), block=192.
//   Phase A: ordered mask compaction for this split (ballot+popc).
//   Phase B: branch-free 8-way batched float4 accumulation (8 LDG.128/thread
//            in flight); partials to g_part.
//   Phase C: last-of-8 block per sample computes count/pooled/logits/NLL
//            (per-sample dependency only — overlaps other samples' pooling).
//   Phase D: last finalizer overall reduces NLLs -> mean loss.
// Ticket visibility follows the canonical threadfenceReduction pattern:
// all writer threads __threadfence() before the ticket atomic.
// No block ever waits on another block -> deadlock-free at any occupancy.
// ---------------------------------------------------------------------------
__global__ __launch_bounds__(VEC_T) void fused_kernel(
    const float* __restrict__ x,
    const void*  __restrict__ mask,
    const float* __restrict__ w,        // [C, D]
    const float* __restrict__ bias,     // [C]
    const int*   __restrict__ labels,   // [B]
    float* __restrict__ logits_out,     // may be nullptr
    float* __restrict__ loss_out)       // may be nullptr
{
    const int b  = blockIdx.x;
    const int sp = blockIdx.y;
    const int t  = threadIdx.x;              // 0..191
    const int s0 = sp * SPB;

    __shared__ int   slist[SPB];
    __shared__ int   wcnt[2];
    __shared__ int   s_kind;
    __shared__ int   s_last_sp;
    __shared__ int   s_last_all;
    __shared__ float red[256];
    __shared__ float r0[256];
    __shared__ float r1[256];
    __shared__ float s_inv;

    if (t == 0) s_kind = detect_mask_kind(mask);
    __syncthreads();
    const int kind = s_kind;

    // --- Phase A: ordered compaction (warps 0 and 1; all lanes active) ---
    int m = 0, pos = 0;
    if (t < 64) {
        const int lane = t & 31;
        const int warp = t >> 5;
        m = mask_at(mask, kind, (size_t)b * S + s0 + t);
        const unsigned bal = __ballot_sync(0xFFFFFFFFu, m);
        pos = __popc(bal & ((1u << lane) - 1u));
        if (lane == 0) wcnt[warp] = __popc(bal);
    }
    __syncthreads();
    if (t < 64 && m) {
        const int base = (t >= 32) ? wcnt[0] : 0;
        slist[base + pos] = s0 + t;          // absolute row index
    }
    __syncthreads();

    const int n = wcnt[0] + wcnt[1];

    // --- Phase B: branch-free batched accumulation (8-way, then 4, then 1) ---
    const float4* __restrict__ xb =
        reinterpret_cast<const float4*>(x + (size_t)b * S * D) + t;

    float4 acc = make_float4(0.f, 0.f, 0.f, 0.f);
    int i = 0;
    for (; i + 8 <= n; i += 8) {
        float4 v[8];
#pragma unroll
        for (int j = 0; j < 8; ++j)
            v[j] = xb[(size_t)slist[i + j] * VEC_T];
#pragma unroll
        for (int j = 0; j < 8; ++j) {
            acc.x += v[j].x; acc.y += v[j].y;
            acc.z += v[j].z; acc.w += v[j].w;
        }
    }
    for (; i + 4 <= n; i += 4) {
        float4 v[4];
#pragma unroll
        for (int j = 0; j < 4; ++j)
            v[j] = xb[(size_t)slist[i + j] * VEC_T];
#pragma unroll
        for (int j = 0; j < 4; ++j) {
            acc.x += v[j].x; acc.y += v[j].y;
            acc.z += v[j].z; acc.w += v[j].w;
        }
    }
    for (; i < n; ++i) {
        const float4 v = xb[(size_t)slist[i] * VEC_T];
        acc.x += v.x; acc.y += v.y; acc.z += v.z; acc.w += v.w;
    }

    reinterpret_cast<float4*>(g_part + ((size_t)sp * B + b) * D)[t] = acc;

    // --- per-sample ticket: publish partials, last-of-8 proceeds ---
    __threadfence();
    __syncthreads();
    if (t == 0) {
        const int old = atomicAdd(&g_sticket[b], 1);
        s_last_sp = (old == SPLIT - 1) ? 1 : 0;
        if (s_last_sp) g_sticket[b] = 0;     // reset for next replay
    }
    __syncthreads();
    if (!s_last_sp) return;

    // =============== Phase C: per-sample finalize (one block) ===============
    // count masked tokens over full S
    float c = 0.f;
    for (int s = t; s < S; s += VEC_T)
        c += (float)mask_at(mask, kind, (size_t)b * S + s);
    red[t] = c;
    if (t < 64) red[192 + t] = 0.f;
    __syncthreads();
    for (int off = 128; off > 0; off >>= 1) {
        if (t < off) red[t] += red[t + off];
        __syncthreads();
    }
    if (t == 0) s_inv = 1.f / red[0];
    __syncthreads();
    const float inv = s_inv;

    // pooled + dot products (each thread owns 4 d-values: 768/192)
    float p0 = 0.f, p1 = 0.f;
#pragma unroll
    for (int k = 0; k < 4; ++k) {
        const int d = t + k * VEC_T;
        float s = 0.f;
#pragma unroll
        for (int q = 0; q < SPLIT; ++q)
            s += g_part[((size_t)q * B + b) * D + d];
        const float pooled = s * inv;
        p0 += pooled * w[d];
        p1 += pooled * w[D + d];
    }
    r0[t] = p0; r1[t] = p1;
    if (t < 64) { r0[192 + t] = 0.f; r1[192 + t] = 0.f; }
    __syncthreads();
    for (int off = 128; off > 0; off >>= 1) {
        if (t < off) { r0[t] += r0[t + off]; r1[t] += r1[t + off]; }
        __syncthreads();
    }

    if (t == 0) {
        const float l0 = r0[0] + bias[0];
        const float l1 = r1[0] + bias[1];
        if (logits_out) {
            logits_out[(size_t)b * C + 0] = l0;
            logits_out[(size_t)b * C + 1] = l1;
        }
        const float mx  = fmaxf(l0, l1);
        const float lse = mx + logf(expf(l0 - mx) + expf(l1 - mx));
        const int lab   = labels[b];
        g_nll[b] = lse - (lab ? l1 : l0);

        __threadfence();
        s_last_all = (atomicAdd(&g_done, 1) == B - 1) ? 1 : 0;
    }
    __syncthreads();

    // =============== Phase D: mean loss (one block overall) ===============
    if (s_last_all) {
        red[t] = g_nll[t];
        if (t < 64) red[192 + t] = g_nll[192 + t];
        __syncthreads();
        for (int off = 128; off > 0; off >>= 1) {
            if (t < off) red[t] += red[t + off];
            __syncthreads();
        }
        if (t == 0) {
            if (loss_out) *loss_out = red[0] * (1.f / (float)B);
            g_done = 0;                  // reset for next replay
        }
    }
}

// ---------------------------------------------------------------------------
extern "C" void kernel_launch(void* const* d_in, const int* in_sizes, int n_in,
                              void* d_out, int out_size)
{
    // Identify inputs by element count (all five mutually distinct).
    const float* x      = nullptr;
    const void*  mask   = nullptr;
    const int*   labels = nullptr;
    const float* w      = nullptr;
    const float* bias   = nullptr;

    for (int i = 0; i < n_in; ++i) {
        switch (in_sizes[i]) {
            case B * S * D: x      = (const float*)d_in[i]; break;
            case B * S:     mask   = d_in[i];               break;
            case B:         labels = (const int*)d_in[i];   break;
            case C * D:     w      = (const float*)d_in[i]; break;
            case C:         bias   = (const float*)d_in[i]; break;
            default: break;
        }
    }
    if (!x)      x      = (const float*)d_in[0];
    if (!mask)   mask   = d_in[1];
    if (!labels) labels = (const int*)d_in[2];
    if (!w)      w      = (const float*)d_in[3];
    if (!bias)   bias   = (const float*)d_in[4];

    float* out = (float*)d_out;

    // Output layout: flattened (loss, logits) = 1 + B*C = 513 floats.
    float* loss_ptr   = nullptr;
    float* logits_ptr = nullptr;
    if (out_size >= 1 + B * C) { loss_ptr = out; logits_ptr = out + 1; }
    else if (out_size == B * C) { logits_ptr = out; }
    else { loss_ptr = out; }

    dim3 g(B, SPLIT);
    fused_kernel<<<g, VEC_T>>>(x, mask, w, bias, labels, logits_ptr, loss_ptr);
}